// round 8
// baseline (speedup 1.0000x reference)
#include <cuda_runtime.h>
#include <cuda_fp16.h>
#include <cstdint>
#include <cstddef>

// ---------------------------------------------------------------------------
// Problem constants
// ---------------------------------------------------------------------------
#define BATCHN   16384
#define INFEAT   512
#define OUTFEAT  512
#define KSPL     8            // grid_size + spline_order
#define NKNOT    12           // grid_size + 2*order + 1
#define KTOT     4608         // INFEAT*KSPL + INFEAT
#define KBASE    4096         // offset of silu block within K

// GEMM tiling: 128x64 CTA tile, 256 threads, 3 CTAs/SM
#define BM 128
#define BN 64
#define BK 64                 // 64 halfs = 128 B per smem row
#define NCHUNK (KTOT / BK)    // 72
#define NSTAGE 3
#define A_BYTES (BM * 128)    // 16 KB
#define B_BYTES (BN * 128)    // 8 KB
#define STAGE_BYTES (A_BYTES + B_BYTES)          // 24 KB
#define SMEM_BYTES (1024 + NSTAGE * STAGE_BYTES) // 74752 (incl. align slack)

// ---------------------------------------------------------------------------
// Global scratch (allocation-free rule: __device__ arrays)
// ---------------------------------------------------------------------------
__device__ __align__(256) __half g_A[(size_t)BATCHN * KTOT];   // activations fp16, K-major
__device__ __align__(256) __half g_W[(size_t)OUTFEAT * KTOT];  // packed weights fp16, K-major
__device__ float g_gv[NKNOT];
__device__ float g_rl[3][11];

// ---------------------------------------------------------------------------
// Helpers
// ---------------------------------------------------------------------------
__device__ __forceinline__ uint32_t smem_u32(const void* p) {
    uint32_t a;
    asm("{ .reg .u64 t; cvta.to.shared.u64 t, %1; cvt.u32.u64 %0, t; }"
        : "=r"(a) : "l"(p));
    return a;
}

__device__ __forceinline__ void cp_async16(uint32_t dst, const void* src) {
    asm volatile("cp.async.cg.shared.global [%0], [%1], 16;"
                 :: "r"(dst), "l"(src) : "memory");
}
#define CP_COMMIT() asm volatile("cp.async.commit_group;" ::: "memory")
#define CP_WAIT1()  asm volatile("cp.async.wait_group 1;" ::: "memory")

__device__ __forceinline__ void ldm_x4(uint32_t* r, uint32_t addr) {
    asm volatile("ldmatrix.sync.aligned.m8n8.x4.shared.b16 {%0,%1,%2,%3}, [%4];"
                 : "=r"(r[0]), "=r"(r[1]), "=r"(r[2]), "=r"(r[3]) : "r"(addr));
}

__device__ __forceinline__ void mma16816(float* d, const uint32_t* a, uint32_t b0, uint32_t b1) {
    asm volatile(
        "mma.sync.aligned.m16n8k16.row.col.f32.f16.f16.f32 "
        "{%0,%1,%2,%3}, {%4,%5,%6,%7}, {%8,%9}, {%0,%1,%2,%3};"
        : "+f"(d[0]), "+f"(d[1]), "+f"(d[2]), "+f"(d[3])
        : "r"(a[0]), "r"(a[1]), "r"(a[2]), "r"(a[3]), "r"(b0), "r"(b1));
}

__device__ __forceinline__ uint32_t pack_h2(float a, float b) {
    __half2 h = __floats2half2_rn(a, b);
    return *reinterpret_cast<uint32_t*>(&h);
}

// swizzle within a 128B row: col-byte ^ ((row&7)<<4)
__device__ __forceinline__ uint32_t swz(int row, int colByte) {
    return (uint32_t)(row * 128 + (colByte ^ ((row & 7) << 4)));
}

// ---------------------------------------------------------------------------
// K0: knots + Cox-de-Boor denominator reciprocals
// ---------------------------------------------------------------------------
__global__ void init_tables_kernel(const float* __restrict__ grid) {
    if (threadIdx.x == 0) {
        float gv[NKNOT];
        #pragma unroll
        for (int j = 0; j < NKNOT; j++) { gv[j] = grid[j]; g_gv[j] = gv[j]; }
        #pragma unroll
        for (int k = 1; k <= 3; k++)
            for (int j = 0; j + k < NKNOT; j++)
                g_rl[k - 1][j] = 1.0f / (gv[j + k] - gv[j]);
    }
}

// ---------------------------------------------------------------------------
// K1: pack weights  W'[o][i*8+k] = spline_w*scaler ; W'[o][4096+i] = base_w
// ---------------------------------------------------------------------------
__global__ void __launch_bounds__(256) pack_w_kernel(
    const float* __restrict__ base_w,
    const float* __restrict__ spline_w,
    const float* __restrict__ scaler)
{
    int idx = blockIdx.x * 256 + threadIdx.x;
    int o = idx >> 9, i = idx & 511;
    float sc = scaler[idx];
    const float4* sp = reinterpret_cast<const float4*>(spline_w + (size_t)idx * KSPL);
    float4 s0 = sp[0], s1 = sp[1];
    uint4 v;
    v.x = pack_h2(s0.x * sc, s0.y * sc);
    v.y = pack_h2(s0.z * sc, s0.w * sc);
    v.z = pack_h2(s1.x * sc, s1.y * sc);
    v.w = pack_h2(s1.z * sc, s1.w * sc);
    *reinterpret_cast<uint4*>(g_W + (size_t)o * KTOT + i * KSPL) = v;
    g_W[(size_t)o * KTOT + KBASE + i] = __float2half_rn(base_w[idx]);
}

// ---------------------------------------------------------------------------
// K2: activations, 4 features per thread
//   A[b][i*8..] = bases(x[b][i]) ; A[b][4096+i] = silu(x[b][i])
// ---------------------------------------------------------------------------
__global__ void __launch_bounds__(256) act_kernel(const float* __restrict__ x)
{
    int idx = blockIdx.x * 256 + threadIdx.x;        // 0 .. 16384*128-1
    int b = idx >> 7, i4 = (idx & 127) * 4;          // 4 consecutive features

    float4 xv4 = *reinterpret_cast<const float4*>(x + (size_t)b * INFEAT + i4);
    float xs[4] = {xv4.x, xv4.y, xv4.z, xv4.w};

    float gv[NKNOT];
    #pragma unroll
    for (int j = 0; j < NKNOT; j++) gv[j] = g_gv[j];
    float rl[3][11];
    #pragma unroll
    for (int k = 0; k < 3; k++)
        #pragma unroll
        for (int j = 0; j < 11 - k; j++) rl[k][j] = g_rl[k][j];

    __half sv[4];
    uint4 vout[4];
    #pragma unroll
    for (int e = 0; e < 4; e++) {
        float xv = xs[e];
        sv[e] = __float2half_rn(xv / (1.0f + expf(-xv)));

        float bb[11];
        #pragma unroll
        for (int j = 0; j < 11; j++)
            bb[j] = (xv >= gv[j] && xv < gv[j + 1]) ? 1.0f : 0.0f;

        #pragma unroll
        for (int k = 1; k <= 3; k++) {
            #pragma unroll
            for (int j = 0; j < 11 - k; j++) {
                float left  = (xv - gv[j]) * rl[k - 1][j] * bb[j];
                float right = (gv[j + k + 1] - xv) * rl[k - 1][j + 1] * bb[j + 1];
                bb[j] = left + right;
            }
        }
        vout[e].x = pack_h2(bb[0], bb[1]);
        vout[e].y = pack_h2(bb[2], bb[3]);
        vout[e].z = pack_h2(bb[4], bb[5]);
        vout[e].w = pack_h2(bb[6], bb[7]);
    }

    uint4* dst = reinterpret_cast<uint4*>(g_A + (size_t)b * KTOT + i4 * KSPL);
    #pragma unroll
    for (int e = 0; e < 4; e++) dst[e] = vout[e];
    *reinterpret_cast<uint2*>(g_A + (size_t)b * KTOT + KBASE + i4) =
        *reinterpret_cast<uint2*>(sv);
}

// ---------------------------------------------------------------------------
// K3: GEMM out[16384,512] = A @ W'^T   (fp16 in, fp32 accum, mma.sync)
// 256 threads, 8 warps (4m x 2n), warp tile 32x32, 3-stage cp.async,
// ONE __syncthreads per chunk, 3 CTAs/SM (1024 tiles / 444 slots).
// ---------------------------------------------------------------------------
__device__ __forceinline__ void load_stage(uint32_t sbd, int stage,
                                           const __half* __restrict__ Ag,
                                           const __half* __restrict__ Bg,
                                           int chunk, int tid)
{
    uint32_t a0 = sbd + stage * STAGE_BYTES;
    uint32_t b0 = a0 + A_BYTES;
    const __half* Ac = Ag + chunk * BK;
    const __half* Bc = Bg + chunk * BK;
    #pragma unroll
    for (int t = 0; t < 4; t++) {                    // A: 1024 x 16B granules
        int g = tid + t * 256;
        int r = g >> 3, c = g & 7;
        cp_async16(a0 + swz(r, c * 16), Ac + (size_t)r * KTOT + c * 8);
    }
    #pragma unroll
    for (int t = 0; t < 2; t++) {                    // B: 512 x 16B granules
        int g = tid + t * 256;
        int r = g >> 3, c = g & 7;
        cp_async16(b0 + swz(r, c * 16), Bc + (size_t)r * KTOT + c * 8);
    }
}

__global__ void __launch_bounds__(256, 3) kan_gemm_kernel(float* __restrict__ out)
{
    extern __shared__ char smem_raw[];
    uint32_t sb_raw = smem_u32(smem_raw);
    uint32_t sbd = (sb_raw + 1023u) & ~1023u;        // swizzle wants clean low bits

    int tid = threadIdx.x, wid = tid >> 5, lid = tid & 31;
    int nt = blockIdx.x, mt = blockIdx.y;
    const __half* Ag = g_A + (size_t)mt * BM * KTOT;
    const __half* Bg = g_W + (size_t)nt * BN * KTOT;

    int wm = (wid >> 1) * 32;                        // warp m offset (4 groups)
    int wn = (wid & 1) * 32;                         // warp n offset (2 groups)

    float d[2][4][4];                                // 32 accum regs
    #pragma unroll
    for (int mi = 0; mi < 2; mi++)
        #pragma unroll
        for (int ni = 0; ni < 4; ni++)
            #pragma unroll
            for (int q = 0; q < 4; q++) d[mi][ni][q] = 0.0f;

    // prologue: stages 0,1
    load_stage(sbd, 0, Ag, Bg, 0, tid); CP_COMMIT();
    load_stage(sbd, 1, Ag, Bg, 1, tid); CP_COMMIT();

    // per-lane ldmatrix address components
    // A (no trans): a0..a3 = m0-7/k0-7, m8-15/k0-7, m0-7/k8-15, m8-15/k8-15
    int a_lane_r = lid & 15;
    int a_lane_c = (lid >> 4) << 4;
    // B (no trans; smem [n][k] is Bmat^T for row.col mma):
    //   b-matrices: n0-7/k0-7, n0-7/k8-15, n8-15/k0-7, n8-15/k8-15
    int b_lane_r = ((lid >> 4) << 3) + (lid & 7);
    int b_lane_c = ((lid >> 3) & 1) << 4;

    uint32_t Af[2][4], Bf[2][4];                     // single-buffer fragments

    for (int c = 0; c < NCHUNK; c++) {
        CP_WAIT1();
        __syncthreads();

        uint32_t a0 = sbd + (c % NSTAGE) * STAGE_BYTES;
        uint32_t b0 = a0 + A_BYTES;

        // ks=0 fragments first (critical path into tensor work)
        #pragma unroll
        for (int mi = 0; mi < 2; mi++)
            ldm_x4(Af[mi], a0 + swz(wm + mi * 16 + a_lane_r, a_lane_c));
        #pragma unroll
        for (int L = 0; L < 2; L++)
            ldm_x4(Bf[L], b0 + swz(wn + L * 16 + b_lane_r, b_lane_c));

        // safe: stage (c+2)%3 == (c-1)%3, finished by all warps before the
        // barrier above (load strictly after sync)
        if (c + 2 < NCHUNK) load_stage(sbd, (c + 2) % NSTAGE, Ag, Bg, c + 2, tid);
        CP_COMMIT();                                 // empty group keeps wait invariant

        #pragma unroll
        for (int ks = 0; ks < 4; ks++) {
            #pragma unroll
            for (int mi = 0; mi < 2; mi++)
                #pragma unroll
                for (int ni = 0; ni < 4; ni++) {
                    const uint32_t* B2 = Bf[ni >> 1] + ((ni & 1) << 1);
                    mma16816(d[mi][ni], Af[mi], B2[0], B2[1]);
                }
            if (ks < 3) {                            // next frags after MMAs issued
                int kb = (ks + 1) * 32;
                #pragma unroll
                for (int mi = 0; mi < 2; mi++)
                    ldm_x4(Af[mi], a0 + swz(wm + mi * 16 + a_lane_r, kb + a_lane_c));
                #pragma unroll
                for (int L = 0; L < 2; L++)
                    ldm_x4(Bf[L], b0 + swz(wn + L * 16 + b_lane_r, kb + b_lane_c));
            }
        }
        // no trailing barrier: next iteration's top barrier provides it
    }

    // epilogue: registers -> gmem (no smem involved, no sync needed)
    int gp = lid >> 2, t4 = lid & 3;
    #pragma unroll
    for (int mi = 0; mi < 2; mi++) {
        int row0 = mt * BM + wm + mi * 16 + gp;
        #pragma unroll
        for (int ni = 0; ni < 4; ni++) {
            int col = nt * BN + wn + ni * 8 + t4 * 2;
            float2 v0 = make_float2(d[mi][ni][0], d[mi][ni][1]);
            float2 v1 = make_float2(d[mi][ni][2], d[mi][ni][3]);
            *reinterpret_cast<float2*>(out + (size_t)row0 * OUTFEAT + col)       = v0;
            *reinterpret_cast<float2*>(out + (size_t)(row0 + 8) * OUTFEAT + col) = v1;
        }
    }
}

// ---------------------------------------------------------------------------
// Launch
// ---------------------------------------------------------------------------
extern "C" void kernel_launch(void* const* d_in, const int* in_sizes, int n_in,
                              void* d_out, int out_size)
{
    const float* x        = (const float*)d_in[0];   // (16384, 512)
    const float* grid     = (const float*)d_in[1];   // (512, 12)
    const float* base_w   = (const float*)d_in[2];   // (512, 512)
    const float* spline_w = (const float*)d_in[3];   // (512, 512, 8)
    const float* scaler   = (const float*)d_in[4];   // (512, 512)
    float* out = (float*)d_out;                      // (16384, 512)

    init_tables_kernel<<<1, 32>>>(grid);
    pack_w_kernel<<<(OUTFEAT * INFEAT) / 256, 256>>>(base_w, spline_w, scaler);
    act_kernel<<<(BATCHN * INFEAT / 4) / 256, 256>>>(x);

    cudaFuncSetAttribute(kan_gemm_kernel,
                         cudaFuncAttributeMaxDynamicSharedMemorySize, SMEM_BYTES);
    dim3 g(OUTFEAT / BN, BATCHN / BM);               // (8, 128), n fastest for L2 reuse
    kan_gemm_kernel<<<g, 256, SMEM_BYTES>>>(out);
}

// round 9
// speedup vs baseline: 1.0416x; 1.0416x over previous
#include <cuda_runtime.h>
#include <cuda_fp16.h>
#include <cstdint>
#include <cstddef>

// ---------------------------------------------------------------------------
// Problem constants
// ---------------------------------------------------------------------------
#define BATCHN   16384
#define INFEAT   512
#define OUTFEAT  512
#define KSPL     8            // grid_size + spline_order
#define NKNOT    12           // grid_size + 2*order + 1
#define KTOT     4608         // INFEAT*KSPL + INFEAT
#define KBASE    4096         // offset of silu block within K

// GEMM tiling: 256x128 CTA tile, 256 threads (8 warps of 64x64), 1 CTA/SM
#define BM 256
#define BN 128
#define BK 64                 // 64 halfs = 128 B per smem row
#define NCHUNK (KTOT / BK)    // 72
#define NSTAGE 3
#define A_BYTES (BM * 128)    // 32 KB
#define B_BYTES (BN * 128)    // 16 KB
#define STAGE_BYTES (A_BYTES + B_BYTES)          // 48 KB
#define SMEM_BYTES (1024 + NSTAGE * STAGE_BYTES) // 148480 (incl. align slack)

// ---------------------------------------------------------------------------
// Global scratch (allocation-free rule: __device__ arrays)
// ---------------------------------------------------------------------------
__device__ __align__(256) __half g_A[(size_t)BATCHN * KTOT];   // activations fp16, K-major
__device__ __align__(256) __half g_W[(size_t)OUTFEAT * KTOT];  // packed weights fp16, K-major
__device__ float g_gv[NKNOT];
__device__ float g_rl[3][11];

// ---------------------------------------------------------------------------
// Helpers
// ---------------------------------------------------------------------------
__device__ __forceinline__ uint32_t smem_u32(const void* p) {
    uint32_t a;
    asm("{ .reg .u64 t; cvta.to.shared.u64 t, %1; cvt.u32.u64 %0, t; }"
        : "=r"(a) : "l"(p));
    return a;
}

__device__ __forceinline__ void cp_async16(uint32_t dst, const void* src) {
    asm volatile("cp.async.cg.shared.global [%0], [%1], 16;"
                 :: "r"(dst), "l"(src) : "memory");
}
#define CP_COMMIT() asm volatile("cp.async.commit_group;" ::: "memory")
#define CP_WAIT1()  asm volatile("cp.async.wait_group 1;" ::: "memory")

__device__ __forceinline__ void ldm_x4(uint32_t* r, uint32_t addr) {
    asm volatile("ldmatrix.sync.aligned.m8n8.x4.shared.b16 {%0,%1,%2,%3}, [%4];"
                 : "=r"(r[0]), "=r"(r[1]), "=r"(r[2]), "=r"(r[3]) : "r"(addr));
}

__device__ __forceinline__ void mma16816(float* d, const uint32_t* a, uint32_t b0, uint32_t b1) {
    asm volatile(
        "mma.sync.aligned.m16n8k16.row.col.f32.f16.f16.f32 "
        "{%0,%1,%2,%3}, {%4,%5,%6,%7}, {%8,%9}, {%0,%1,%2,%3};"
        : "+f"(d[0]), "+f"(d[1]), "+f"(d[2]), "+f"(d[3])
        : "r"(a[0]), "r"(a[1]), "r"(a[2]), "r"(a[3]), "r"(b0), "r"(b1));
}

__device__ __forceinline__ uint32_t pack_h2(float a, float b) {
    __half2 h = __floats2half2_rn(a, b);
    return *reinterpret_cast<uint32_t*>(&h);
}

// swizzle within a 128B row: col-byte ^ ((row&7)<<4)
__device__ __forceinline__ uint32_t swz(int row, int colByte) {
    return (uint32_t)(row * 128 + (colByte ^ ((row & 7) << 4)));
}

// ---------------------------------------------------------------------------
// K0: knots + Cox-de-Boor denominator reciprocals
// ---------------------------------------------------------------------------
__global__ void init_tables_kernel(const float* __restrict__ grid) {
    if (threadIdx.x == 0) {
        float gv[NKNOT];
        #pragma unroll
        for (int j = 0; j < NKNOT; j++) { gv[j] = grid[j]; g_gv[j] = gv[j]; }
        #pragma unroll
        for (int k = 1; k <= 3; k++)
            for (int j = 0; j + k < NKNOT; j++)
                g_rl[k - 1][j] = 1.0f / (gv[j + k] - gv[j]);
    }
}

// ---------------------------------------------------------------------------
// K1: pack weights  W'[o][i*8+k] = spline_w*scaler ; W'[o][4096+i] = base_w
// ---------------------------------------------------------------------------
__global__ void __launch_bounds__(256) pack_w_kernel(
    const float* __restrict__ base_w,
    const float* __restrict__ spline_w,
    const float* __restrict__ scaler)
{
    int idx = blockIdx.x * 256 + threadIdx.x;
    int o = idx >> 9, i = idx & 511;
    float sc = scaler[idx];
    const float4* sp = reinterpret_cast<const float4*>(spline_w + (size_t)idx * KSPL);
    float4 s0 = sp[0], s1 = sp[1];
    uint4 v;
    v.x = pack_h2(s0.x * sc, s0.y * sc);
    v.y = pack_h2(s0.z * sc, s0.w * sc);
    v.z = pack_h2(s1.x * sc, s1.y * sc);
    v.w = pack_h2(s1.z * sc, s1.w * sc);
    *reinterpret_cast<uint4*>(g_W + (size_t)o * KTOT + i * KSPL) = v;
    g_W[(size_t)o * KTOT + KBASE + i] = __float2half_rn(base_w[idx]);
}

// ---------------------------------------------------------------------------
// K2: activations, 4 features per thread
//   A[b][i*8..] = bases(x[b][i]) ; A[b][4096+i] = silu(x[b][i])
// ---------------------------------------------------------------------------
__global__ void __launch_bounds__(256) act_kernel(const float* __restrict__ x)
{
    int idx = blockIdx.x * 256 + threadIdx.x;        // 0 .. 16384*128-1
    int b = idx >> 7, i4 = (idx & 127) * 4;          // 4 consecutive features

    float4 xv4 = *reinterpret_cast<const float4*>(x + (size_t)b * INFEAT + i4);
    float xs[4] = {xv4.x, xv4.y, xv4.z, xv4.w};

    float gv[NKNOT];
    #pragma unroll
    for (int j = 0; j < NKNOT; j++) gv[j] = g_gv[j];
    float rl[3][11];
    #pragma unroll
    for (int k = 0; k < 3; k++)
        #pragma unroll
        for (int j = 0; j < 11 - k; j++) rl[k][j] = g_rl[k][j];

    __half sv[4];
    uint4 vout[4];
    #pragma unroll
    for (int e = 0; e < 4; e++) {
        float xv = xs[e];
        sv[e] = __float2half_rn(xv / (1.0f + expf(-xv)));

        float bb[11];
        #pragma unroll
        for (int j = 0; j < 11; j++)
            bb[j] = (xv >= gv[j] && xv < gv[j + 1]) ? 1.0f : 0.0f;

        #pragma unroll
        for (int k = 1; k <= 3; k++) {
            #pragma unroll
            for (int j = 0; j < 11 - k; j++) {
                float left  = (xv - gv[j]) * rl[k - 1][j] * bb[j];
                float right = (gv[j + k + 1] - xv) * rl[k - 1][j + 1] * bb[j + 1];
                bb[j] = left + right;
            }
        }
        vout[e].x = pack_h2(bb[0], bb[1]);
        vout[e].y = pack_h2(bb[2], bb[3]);
        vout[e].z = pack_h2(bb[4], bb[5]);
        vout[e].w = pack_h2(bb[6], bb[7]);
    }

    uint4* dst = reinterpret_cast<uint4*>(g_A + (size_t)b * KTOT + i4 * KSPL);
    #pragma unroll
    for (int e = 0; e < 4; e++) dst[e] = vout[e];
    *reinterpret_cast<uint2*>(g_A + (size_t)b * KTOT + KBASE + i4) =
        *reinterpret_cast<uint2*>(sv);
}

// ---------------------------------------------------------------------------
// K3: GEMM out[16384,512] = A @ W'^T   (fp16 in, fp32 accum, mma.sync)
// 256 threads, 8 warps (4m x 2n) of 64x64 warp tiles, 3-stage cp.async,
// ONE __syncthreads per chunk, 1 CTA/SM (grid 256).
// 64x64 warp tile: 32 MMAs per 8 ldm_x4 -> 33% less smem traffic per MMA.
// ---------------------------------------------------------------------------
__device__ __forceinline__ void load_stage(uint32_t sbd, int stage,
                                           const __half* __restrict__ Ag,
                                           const __half* __restrict__ Bg,
                                           int chunk, int tid)
{
    uint32_t a0 = sbd + stage * STAGE_BYTES;
    uint32_t b0 = a0 + A_BYTES;
    const __half* Ac = Ag + chunk * BK;
    const __half* Bc = Bg + chunk * BK;
    #pragma unroll
    for (int t = 0; t < 8; t++) {                    // A: 2048 x 16B granules
        int g = tid + t * 256;
        int r = g >> 3, c = g & 7;
        cp_async16(a0 + swz(r, c * 16), Ac + (size_t)r * KTOT + c * 8);
    }
    #pragma unroll
    for (int t = 0; t < 4; t++) {                    // B: 1024 x 16B granules
        int g = tid + t * 256;
        int r = g >> 3, c = g & 7;
        cp_async16(b0 + swz(r, c * 16), Bc + (size_t)r * KTOT + c * 8);
    }
}

__global__ void __launch_bounds__(256, 1) kan_gemm_kernel(float* __restrict__ out)
{
    extern __shared__ char smem_raw[];
    uint32_t sb_raw = smem_u32(smem_raw);
    uint32_t sbd = (sb_raw + 1023u) & ~1023u;        // swizzle wants clean low bits

    int tid = threadIdx.x, wid = tid >> 5, lid = tid & 31;
    int nt = blockIdx.x, mt = blockIdx.y;
    const __half* Ag = g_A + (size_t)mt * BM * KTOT;
    const __half* Bg = g_W + (size_t)nt * BN * KTOT;

    int wm = (wid >> 1) * 64;                        // warp m offset (4 groups)
    int wn = (wid & 1) * 64;                         // warp n offset (2 groups)

    float d[4][8][4];                                // 128 accum regs
    #pragma unroll
    for (int mi = 0; mi < 4; mi++)
        #pragma unroll
        for (int ni = 0; ni < 8; ni++)
            #pragma unroll
            for (int q = 0; q < 4; q++) d[mi][ni][q] = 0.0f;

    // prologue: stages 0,1
    load_stage(sbd, 0, Ag, Bg, 0, tid); CP_COMMIT();
    load_stage(sbd, 1, Ag, Bg, 1, tid); CP_COMMIT();

    // per-lane ldmatrix address components
    // A (no trans): a0..a3 = m0-7/k0-7, m8-15/k0-7, m0-7/k8-15, m8-15/k8-15
    int a_lane_r = lid & 15;
    int a_lane_c = (lid >> 4) << 4;
    // B (no trans; smem [n][k] is Bmat^T for row.col mma):
    //   b-matrices: n0-7/k0-7, n0-7/k8-15, n8-15/k0-7, n8-15/k8-15
    int b_lane_r = ((lid >> 4) << 3) + (lid & 7);
    int b_lane_c = ((lid >> 3) & 1) << 4;

    uint32_t Af[4][4], Bf[4][4];                     // 64x64 warp tile fragments

    for (int c = 0; c < NCHUNK; c++) {
        CP_WAIT1();
        __syncthreads();
        // safe: stage (c+2)%3 == (c-1)%3, finished by all warps before the
        // barrier above (load strictly after sync)
        if (c + 2 < NCHUNK) load_stage(sbd, (c + 2) % NSTAGE, Ag, Bg, c + 2, tid);
        CP_COMMIT();                                 // empty group keeps wait invariant

        uint32_t a0 = sbd + (c % NSTAGE) * STAGE_BYTES;
        uint32_t b0 = a0 + A_BYTES;

        #pragma unroll
        for (int ks = 0; ks < 4; ks++) {
            int kb = ks * 32;                        // 16 halfs = 32 bytes
            #pragma unroll
            for (int mi = 0; mi < 4; mi++)
                ldm_x4(Af[mi], a0 + swz(wm + mi * 16 + a_lane_r, kb + a_lane_c));
            #pragma unroll
            for (int L = 0; L < 4; L++)
                ldm_x4(Bf[L], b0 + swz(wn + L * 16 + b_lane_r, kb + b_lane_c));
            #pragma unroll
            for (int mi = 0; mi < 4; mi++)
                #pragma unroll
                for (int ni = 0; ni < 8; ni++) {
                    const uint32_t* B2 = Bf[ni >> 1] + ((ni & 1) << 1);
                    mma16816(d[mi][ni], Af[mi], B2[0], B2[1]);
                }
        }
        // no trailing barrier: next iteration's top barrier provides it
    }

    // epilogue: registers -> gmem (no smem involved, no sync needed)
    int gp = lid >> 2, t4 = lid & 3;
    #pragma unroll
    for (int mi = 0; mi < 4; mi++) {
        int row0 = mt * BM + wm + mi * 16 + gp;
        #pragma unroll
        for (int ni = 0; ni < 8; ni++) {
            int col = nt * BN + wn + ni * 8 + t4 * 2;
            float2 v0 = make_float2(d[mi][ni][0], d[mi][ni][1]);
            float2 v1 = make_float2(d[mi][ni][2], d[mi][ni][3]);
            *reinterpret_cast<float2*>(out + (size_t)row0 * OUTFEAT + col)       = v0;
            *reinterpret_cast<float2*>(out + (size_t)(row0 + 8) * OUTFEAT + col) = v1;
        }
    }
}

// ---------------------------------------------------------------------------
// Launch
// ---------------------------------------------------------------------------
extern "C" void kernel_launch(void* const* d_in, const int* in_sizes, int n_in,
                              void* d_out, int out_size)
{
    const float* x        = (const float*)d_in[0];   // (16384, 512)
    const float* grid     = (const float*)d_in[1];   // (512, 12)
    const float* base_w   = (const float*)d_in[2];   // (512, 512)
    const float* spline_w = (const float*)d_in[3];   // (512, 512, 8)
    const float* scaler   = (const float*)d_in[4];   // (512, 512)
    float* out = (float*)d_out;                      // (16384, 512)

    init_tables_kernel<<<1, 32>>>(grid);
    pack_w_kernel<<<(OUTFEAT * INFEAT) / 256, 256>>>(base_w, spline_w, scaler);
    act_kernel<<<(BATCHN * INFEAT / 4) / 256, 256>>>(x);

    cudaFuncSetAttribute(kan_gemm_kernel,
                         cudaFuncAttributeMaxDynamicSharedMemorySize, SMEM_BYTES);
    dim3 g(OUTFEAT / BN, BATCHN / BM);               // (4, 64), n fastest for L2 reuse
    kan_gemm_kernel<<<g, 256, SMEM_BYTES>>>(out);
}

// round 10
// speedup vs baseline: 1.0558x; 1.0136x over previous
#include <cuda_runtime.h>
#include <cuda_fp16.h>
#include <cstdint>
#include <cstddef>

// ---------------------------------------------------------------------------
// Problem constants
// ---------------------------------------------------------------------------
#define BATCHN   16384
#define INFEAT   512
#define OUTFEAT  512
#define KSPL     8            // grid_size + spline_order
#define NKNOT    12           // grid_size + 2*order + 1
#define KTOT     4608         // INFEAT*KSPL + INFEAT
#define KBASE    4096         // offset of silu block within K

// GEMM tiling: 128x128 CTA tile, 256 threads, 2 CTAs/SM (best known: R5)
#define BM 128
#define BN 128
#define BK 64                 // 64 halfs = 128 B per smem row
#define NCHUNK (KTOT / BK)    // 72
#define NSTAGE 3
#define A_BYTES (BM * 128)    // 16 KB
#define B_BYTES (BN * 128)    // 16 KB
#define STAGE_BYTES (A_BYTES + B_BYTES)          // 32 KB
#define SMEM_BYTES (1024 + NSTAGE * STAGE_BYTES) // 99328 (incl. align slack)

// ---------------------------------------------------------------------------
// Global scratch (allocation-free rule: __device__ arrays)
// ---------------------------------------------------------------------------
__device__ __align__(256) __half g_A[(size_t)BATCHN * KTOT];   // activations fp16, K-major
__device__ __align__(256) __half g_W[(size_t)OUTFEAT * KTOT];  // packed weights fp16, K-major
__device__ float g_gv[NKNOT];
__device__ float g_rl[3][11];

// ---------------------------------------------------------------------------
// Helpers
// ---------------------------------------------------------------------------
__device__ __forceinline__ uint32_t smem_u32(const void* p) {
    uint32_t a;
    asm("{ .reg .u64 t; cvta.to.shared.u64 t, %1; cvt.u32.u64 %0, t; }"
        : "=r"(a) : "l"(p));
    return a;
}

__device__ __forceinline__ void cp_async16(uint32_t dst, const void* src) {
    asm volatile("cp.async.cg.shared.global [%0], [%1], 16;"
                 :: "r"(dst), "l"(src) : "memory");
}
#define CP_COMMIT() asm volatile("cp.async.commit_group;" ::: "memory")
#define CP_WAIT1()  asm volatile("cp.async.wait_group 1;" ::: "memory")

__device__ __forceinline__ void ldm_x4(uint32_t* r, uint32_t addr) {
    asm volatile("ldmatrix.sync.aligned.m8n8.x4.shared.b16 {%0,%1,%2,%3}, [%4];"
                 : "=r"(r[0]), "=r"(r[1]), "=r"(r[2]), "=r"(r[3]) : "r"(addr));
}

__device__ __forceinline__ void mma16816(float* d, const uint32_t* a, uint32_t b0, uint32_t b1) {
    asm volatile(
        "mma.sync.aligned.m16n8k16.row.col.f32.f16.f16.f32 "
        "{%0,%1,%2,%3}, {%4,%5,%6,%7}, {%8,%9}, {%0,%1,%2,%3};"
        : "+f"(d[0]), "+f"(d[1]), "+f"(d[2]), "+f"(d[3])
        : "r"(a[0]), "r"(a[1]), "r"(a[2]), "r"(a[3]), "r"(b0), "r"(b1));
}

__device__ __forceinline__ uint32_t pack_h2(float a, float b) {
    __half2 h = __floats2half2_rn(a, b);
    return *reinterpret_cast<uint32_t*>(&h);
}

// swizzle within a 128B row: col-byte ^ ((row&7)<<4)
__device__ __forceinline__ uint32_t swz(int row, int colByte) {
    return (uint32_t)(row * 128 + (colByte ^ ((row & 7) << 4)));
}

// ---------------------------------------------------------------------------
// K0: knots + Cox-de-Boor denominator reciprocals
// ---------------------------------------------------------------------------
__global__ void init_tables_kernel(const float* __restrict__ grid) {
    if (threadIdx.x == 0) {
        float gv[NKNOT];
        #pragma unroll
        for (int j = 0; j < NKNOT; j++) { gv[j] = grid[j]; g_gv[j] = gv[j]; }
        #pragma unroll
        for (int k = 1; k <= 3; k++)
            for (int j = 0; j + k < NKNOT; j++)
                g_rl[k - 1][j] = 1.0f / (gv[j + k] - gv[j]);
    }
}

// ---------------------------------------------------------------------------
// K1: pack weights  W'[o][i*8+k] = spline_w*scaler ; W'[o][4096+i] = base_w
// ---------------------------------------------------------------------------
__global__ void __launch_bounds__(256) pack_w_kernel(
    const float* __restrict__ base_w,
    const float* __restrict__ spline_w,
    const float* __restrict__ scaler)
{
    int idx = blockIdx.x * 256 + threadIdx.x;
    int o = idx >> 9, i = idx & 511;
    float sc = scaler[idx];
    const float4* sp = reinterpret_cast<const float4*>(spline_w + (size_t)idx * KSPL);
    float4 s0 = sp[0], s1 = sp[1];
    uint4 v;
    v.x = pack_h2(s0.x * sc, s0.y * sc);
    v.y = pack_h2(s0.z * sc, s0.w * sc);
    v.z = pack_h2(s1.x * sc, s1.y * sc);
    v.w = pack_h2(s1.z * sc, s1.w * sc);
    *reinterpret_cast<uint4*>(g_W + (size_t)o * KTOT + i * KSPL) = v;
    g_W[(size_t)o * KTOT + KBASE + i] = __float2half_rn(base_w[idx]);
}

// ---------------------------------------------------------------------------
// K2: activations, 4 features per thread
//   A[b][i*8..] = bases(x[b][i]) ; A[b][4096+i] = silu(x[b][i])
// ---------------------------------------------------------------------------
__global__ void __launch_bounds__(256) act_kernel(const float* __restrict__ x)
{
    int idx = blockIdx.x * 256 + threadIdx.x;        // 0 .. 16384*128-1
    int b = idx >> 7, i4 = (idx & 127) * 4;          // 4 consecutive features

    float4 xv4 = *reinterpret_cast<const float4*>(x + (size_t)b * INFEAT + i4);
    float xs[4] = {xv4.x, xv4.y, xv4.z, xv4.w};

    float gv[NKNOT];
    #pragma unroll
    for (int j = 0; j < NKNOT; j++) gv[j] = g_gv[j];
    float rl[3][11];
    #pragma unroll
    for (int k = 0; k < 3; k++)
        #pragma unroll
        for (int j = 0; j < 11 - k; j++) rl[k][j] = g_rl[k][j];

    __half sv[4];
    uint4 vout[4];
    #pragma unroll
    for (int e = 0; e < 4; e++) {
        float xv = xs[e];
        sv[e] = __float2half_rn(xv / (1.0f + expf(-xv)));

        float bb[11];
        #pragma unroll
        for (int j = 0; j < 11; j++)
            bb[j] = (xv >= gv[j] && xv < gv[j + 1]) ? 1.0f : 0.0f;

        #pragma unroll
        for (int k = 1; k <= 3; k++) {
            #pragma unroll
            for (int j = 0; j < 11 - k; j++) {
                float left  = (xv - gv[j]) * rl[k - 1][j] * bb[j];
                float right = (gv[j + k + 1] - xv) * rl[k - 1][j + 1] * bb[j + 1];
                bb[j] = left + right;
            }
        }
        vout[e].x = pack_h2(bb[0], bb[1]);
        vout[e].y = pack_h2(bb[2], bb[3]);
        vout[e].z = pack_h2(bb[4], bb[5]);
        vout[e].w = pack_h2(bb[6], bb[7]);
    }

    uint4* dst = reinterpret_cast<uint4*>(g_A + (size_t)b * KTOT + i4 * KSPL);
    #pragma unroll
    for (int e = 0; e < 4; e++) dst[e] = vout[e];
    *reinterpret_cast<uint2*>(g_A + (size_t)b * KTOT + KBASE + i4) =
        *reinterpret_cast<uint2*>(sv);
}

// ---------------------------------------------------------------------------
// K3: GEMM out[16384,512] = A @ W'^T   (fp16 in, fp32 accum, mma.sync)
// 256 threads, 8 warps (2m x 4n), warp tile 64x32, 3-stage cp.async,
// ONE __syncthreads per chunk, 2 CTAs/SM.
// K-chunk order staggered per CTA (start = (bid%3)*24) so co-resident CTAs
// run decorrelated pipeline phases: one CTA's barrier/LDSM window overlaps
// the other's MMA burst instead of colliding with it.
// ---------------------------------------------------------------------------
__device__ __forceinline__ void load_stage(uint32_t sbd, int stage,
                                           const __half* __restrict__ Ag,
                                           const __half* __restrict__ Bg,
                                           int chunk, int tid)
{
    uint32_t a0 = sbd + stage * STAGE_BYTES;
    uint32_t b0 = a0 + A_BYTES;
    const __half* Ac = Ag + chunk * BK;
    const __half* Bc = Bg + chunk * BK;
    #pragma unroll
    for (int t = 0; t < 4; t++) {                    // A: 1024 x 16B granules
        int g = tid + t * 256;
        int r = g >> 3, c = g & 7;
        cp_async16(a0 + swz(r, c * 16), Ac + (size_t)r * KTOT + c * 8);
    }
    #pragma unroll
    for (int t = 0; t < 4; t++) {                    // B: 1024 x 16B granules
        int g = tid + t * 256;
        int r = g >> 3, c = g & 7;
        cp_async16(b0 + swz(r, c * 16), Bc + (size_t)r * KTOT + c * 8);
    }
}

__global__ void __launch_bounds__(256, 2) kan_gemm_kernel(float* __restrict__ out)
{
    extern __shared__ char smem_raw[];
    uint32_t sb_raw = smem_u32(smem_raw);
    uint32_t sbd = (sb_raw + 1023u) & ~1023u;        // swizzle wants clean low bits

    int tid = threadIdx.x, wid = tid >> 5, lid = tid & 31;
    int nt = blockIdx.x, mt = blockIdx.y;
    const __half* Ag = g_A + (size_t)mt * BM * KTOT;
    const __half* Bg = g_W + (size_t)nt * BN * KTOT;

    // per-CTA chunk-order stagger (accumulation is commutative)
    int start = ((mt * 4 + nt) % 3) * 24;            // 0 / 24 / 48

    int wm = (wid >> 2) * 64;                        // warp m offset (2 groups)
    int wn = (wid & 3) * 32;                         // warp n offset (4 groups)

    float d[4][4][4];
    #pragma unroll
    for (int mi = 0; mi < 4; mi++)
        #pragma unroll
        for (int ni = 0; ni < 4; ni++)
            #pragma unroll
            for (int q = 0; q < 4; q++) d[mi][ni][q] = 0.0f;

    // prologue: stages 0,1 hold chunks start, start+1
    {
        int ch1 = start + 1; if (ch1 >= NCHUNK) ch1 -= NCHUNK;
        load_stage(sbd, 0, Ag, Bg, start, tid); CP_COMMIT();
        load_stage(sbd, 1, Ag, Bg, ch1, tid);  CP_COMMIT();
    }

    // per-lane ldmatrix address components
    // A (no trans): a0..a3 = m0-7/k0-7, m8-15/k0-7, m0-7/k8-15, m8-15/k8-15
    int a_lane_r = lid & 15;
    int a_lane_c = (lid >> 4) << 4;
    // B (no trans; smem [n][k] is Bmat^T for row.col mma):
    //   b-matrices: n0-7/k0-7, n0-7/k8-15, n8-15/k0-7, n8-15/k8-15
    int b_lane_r = ((lid >> 4) << 3) + (lid & 7);
    int b_lane_c = ((lid >> 3) & 1) << 4;

    uint32_t Af[4][4], Bf[2][4];                     // single-buffer fragments

    for (int c = 0; c < NCHUNK; c++) {
        CP_WAIT1();
        __syncthreads();

        uint32_t a0 = sbd + (c % NSTAGE) * STAGE_BYTES;
        uint32_t b0 = a0 + A_BYTES;

        // ks=0 fragments first (critical path into tensor work)
        #pragma unroll
        for (int mi = 0; mi < 4; mi++)
            ldm_x4(Af[mi], a0 + swz(wm + mi * 16 + a_lane_r, a_lane_c));
        #pragma unroll
        for (int L = 0; L < 2; L++)
            ldm_x4(Bf[L], b0 + swz(wn + L * 16 + b_lane_r, b_lane_c));

        // safe: stage (c+2)%3 == (c-1)%3, finished by all warps before the
        // barrier above (load strictly after sync)
        if (c + 2 < NCHUNK) {
            int ch = start + c + 2; if (ch >= NCHUNK) ch -= NCHUNK;
            load_stage(sbd, (c + 2) % NSTAGE, Ag, Bg, ch, tid);
        }
        CP_COMMIT();                                 // empty group keeps wait invariant

        #pragma unroll
        for (int ks = 0; ks < 4; ks++) {
            #pragma unroll
            for (int mi = 0; mi < 4; mi++)
                #pragma unroll
                for (int ni = 0; ni < 4; ni++) {
                    const uint32_t* B2 = Bf[ni >> 1] + ((ni & 1) << 1);
                    mma16816(d[mi][ni], Af[mi], B2[0], B2[1]);
                }
            if (ks < 3) {                            // next frags after MMAs issued
                int kb = (ks + 1) * 32;
                #pragma unroll
                for (int mi = 0; mi < 4; mi++)
                    ldm_x4(Af[mi], a0 + swz(wm + mi * 16 + a_lane_r, kb + a_lane_c));
                #pragma unroll
                for (int L = 0; L < 2; L++)
                    ldm_x4(Bf[L], b0 + swz(wn + L * 16 + b_lane_r, kb + b_lane_c));
            }
        }
        // no trailing barrier: next iteration's top barrier provides it
    }

    // epilogue: registers -> gmem (no smem involved, no sync needed)
    int gp = lid >> 2, t4 = lid & 3;
    #pragma unroll
    for (int mi = 0; mi < 4; mi++) {
        int row0 = mt * BM + wm + mi * 16 + gp;
        #pragma unroll
        for (int ni = 0; ni < 4; ni++) {
            int col = nt * BN + wn + ni * 8 + t4 * 2;
            float2 v0 = make_float2(d[mi][ni][0], d[mi][ni][1]);
            float2 v1 = make_float2(d[mi][ni][2], d[mi][ni][3]);
            *reinterpret_cast<float2*>(out + (size_t)row0 * OUTFEAT + col)       = v0;
            *reinterpret_cast<float2*>(out + (size_t)(row0 + 8) * OUTFEAT + col) = v1;
        }
    }
}

// ---------------------------------------------------------------------------
// Launch
// ---------------------------------------------------------------------------
extern "C" void kernel_launch(void* const* d_in, const int* in_sizes, int n_in,
                              void* d_out, int out_size)
{
    const float* x        = (const float*)d_in[0];   // (16384, 512)
    const float* grid     = (const float*)d_in[1];   // (512, 12)
    const float* base_w   = (const float*)d_in[2];   // (512, 512)
    const float* spline_w = (const float*)d_in[3];   // (512, 512, 8)
    const float* scaler   = (const float*)d_in[4];   // (512, 512)
    float* out = (float*)d_out;                      // (16384, 512)

    init_tables_kernel<<<1, 32>>>(grid);
    pack_w_kernel<<<(OUTFEAT * INFEAT) / 256, 256>>>(base_w, spline_w, scaler);
    act_kernel<<<(BATCHN * INFEAT / 4) / 256, 256>>>(x);

    cudaFuncSetAttribute(kan_gemm_kernel,
                         cudaFuncAttributeMaxDynamicSharedMemorySize, SMEM_BYTES);
    dim3 g(OUTFEAT / BN, BATCHN / BM);               // (4, 128), n fastest for L2 reuse
    kan_gemm_kernel<<<g, 256, SMEM_BYTES>>>(out);
}

// round 11
// speedup vs baseline: 1.0970x; 1.0390x over previous
#include <cuda_runtime.h>
#include <cuda_fp16.h>
#include <cstdint>
#include <cstddef>

// ---------------------------------------------------------------------------
// Problem constants
// ---------------------------------------------------------------------------
#define BATCHN   16384
#define INFEAT   512
#define OUTFEAT  512
#define KSPL     8            // grid_size + spline_order
#define NKNOT    12           // grid_size + 2*order + 1
#define KTOT     4608         // INFEAT*KSPL + INFEAT
#define KBASE    4096         // offset of silu block within K

// GEMM tiling: 128x128 CTA tile, 256 threads, 2 CTAs/SM (best known: R5)
#define BM 128
#define BN 128
#define BK 64                 // 64 halfs = 128 B per smem row
#define NCHUNK (KTOT / BK)    // 72
#define NSTAGE 3
#define A_BYTES (BM * 128)    // 16 KB
#define B_BYTES (BN * 128)    // 16 KB
#define STAGE_BYTES (A_BYTES + B_BYTES)          // 32 KB
#define SMEM_BYTES (1024 + NSTAGE * STAGE_BYTES) // 99328 (incl. align slack)

// ---------------------------------------------------------------------------
// Global scratch (allocation-free rule: __device__ arrays)
// ---------------------------------------------------------------------------
__device__ __align__(256) __half g_A[(size_t)BATCHN * KTOT];   // activations fp16, K-major
__device__ __align__(256) __half g_W[(size_t)OUTFEAT * KTOT];  // packed weights fp16, K-major
__device__ float g_gv[NKNOT];
__device__ float g_rl[3][11];

// ---------------------------------------------------------------------------
// Helpers
// ---------------------------------------------------------------------------
__device__ __forceinline__ uint32_t smem_u32(const void* p) {
    uint32_t a;
    asm("{ .reg .u64 t; cvta.to.shared.u64 t, %1; cvt.u32.u64 %0, t; }"
        : "=r"(a) : "l"(p));
    return a;
}

__device__ __forceinline__ void cp_async16(uint32_t dst, const void* src) {
    asm volatile("cp.async.cg.shared.global [%0], [%1], 16;"
                 :: "r"(dst), "l"(src) : "memory");
}
#define CP_COMMIT() asm volatile("cp.async.commit_group;" ::: "memory")
#define CP_WAIT1()  asm volatile("cp.async.wait_group 1;" ::: "memory")

__device__ __forceinline__ void ldm_x4(uint32_t* r, uint32_t addr) {
    asm volatile("ldmatrix.sync.aligned.m8n8.x4.shared.b16 {%0,%1,%2,%3}, [%4];"
                 : "=r"(r[0]), "=r"(r[1]), "=r"(r[2]), "=r"(r[3]) : "r"(addr));
}

__device__ __forceinline__ void mma16816(float* d, const uint32_t* a, uint32_t b0, uint32_t b1) {
    asm volatile(
        "mma.sync.aligned.m16n8k16.row.col.f32.f16.f16.f32 "
        "{%0,%1,%2,%3}, {%4,%5,%6,%7}, {%8,%9}, {%0,%1,%2,%3};"
        : "+f"(d[0]), "+f"(d[1]), "+f"(d[2]), "+f"(d[3])
        : "r"(a[0]), "r"(a[1]), "r"(a[2]), "r"(a[3]), "r"(b0), "r"(b1));
}

__device__ __forceinline__ uint32_t pack_h2(float a, float b) {
    __half2 h = __floats2half2_rn(a, b);
    return *reinterpret_cast<uint32_t*>(&h);
}

// swizzle within a 128B row: col-byte ^ ((row&7)<<4)
__device__ __forceinline__ uint32_t swz(int row, int colByte) {
    return (uint32_t)(row * 128 + (colByte ^ ((row & 7) << 4)));
}

// ---------------------------------------------------------------------------
// K0: knots + Cox-de-Boor denominator reciprocals
// ---------------------------------------------------------------------------
__global__ void init_tables_kernel(const float* __restrict__ grid) {
    if (threadIdx.x == 0) {
        float gv[NKNOT];
        #pragma unroll
        for (int j = 0; j < NKNOT; j++) { gv[j] = grid[j]; g_gv[j] = gv[j]; }
        #pragma unroll
        for (int k = 1; k <= 3; k++)
            for (int j = 0; j + k < NKNOT; j++)
                g_rl[k - 1][j] = 1.0f / (gv[j + k] - gv[j]);
    }
}

// ---------------------------------------------------------------------------
// K1: pack weights  W'[o][i*8+k] = spline_w*scaler ; W'[o][4096+i] = base_w
// ---------------------------------------------------------------------------
__global__ void __launch_bounds__(256) pack_w_kernel(
    const float* __restrict__ base_w,
    const float* __restrict__ spline_w,
    const float* __restrict__ scaler)
{
    int idx = blockIdx.x * 256 + threadIdx.x;
    int o = idx >> 9, i = idx & 511;
    float sc = scaler[idx];
    const float4* sp = reinterpret_cast<const float4*>(spline_w + (size_t)idx * KSPL);
    float4 s0 = sp[0], s1 = sp[1];
    uint4 v;
    v.x = pack_h2(s0.x * sc, s0.y * sc);
    v.y = pack_h2(s0.z * sc, s0.w * sc);
    v.z = pack_h2(s1.x * sc, s1.y * sc);
    v.w = pack_h2(s1.z * sc, s1.w * sc);
    *reinterpret_cast<uint4*>(g_W + (size_t)o * KTOT + i * KSPL) = v;
    g_W[(size_t)o * KTOT + KBASE + i] = __float2half_rn(base_w[idx]);
}

// ---------------------------------------------------------------------------
// K2: activations, 4 features per thread, fast-path exp
//   A[b][i*8..] = bases(x[b][i]) ; A[b][4096+i] = silu(x[b][i])
// ---------------------------------------------------------------------------
__global__ void __launch_bounds__(256) act_kernel(const float* __restrict__ x)
{
    int idx = blockIdx.x * 256 + threadIdx.x;        // 0 .. 16384*128-1
    int b = idx >> 7, i4 = (idx & 127) * 4;          // 4 consecutive features

    float4 xv4 = *reinterpret_cast<const float4*>(x + (size_t)b * INFEAT + i4);
    float xs[4] = {xv4.x, xv4.y, xv4.z, xv4.w};

    float gv[NKNOT];
    #pragma unroll
    for (int j = 0; j < NKNOT; j++) gv[j] = g_gv[j];
    float rl[3][11];
    #pragma unroll
    for (int k = 0; k < 3; k++)
        #pragma unroll
        for (int j = 0; j < 11 - k; j++) rl[k][j] = g_rl[k][j];

    __half sv[4];
    uint4 vout[4];
    #pragma unroll
    for (int e = 0; e < 4; e++) {
        float xv = xs[e];
        // silu via guaranteed-fast exp (1 MUFU EX2); ~2ulp error, far below
        // the fp16 quantization already applied to A
        sv[e] = __float2half_rn(xv / (1.0f + __expf(-xv)));

        float bb[11];
        #pragma unroll
        for (int j = 0; j < 11; j++)
            bb[j] = (xv >= gv[j] && xv < gv[j + 1]) ? 1.0f : 0.0f;

        #pragma unroll
        for (int k = 1; k <= 3; k++) {
            #pragma unroll
            for (int j = 0; j < 11 - k; j++) {
                float left  = (xv - gv[j]) * rl[k - 1][j] * bb[j];
                float right = (gv[j + k + 1] - xv) * rl[k - 1][j + 1] * bb[j + 1];
                bb[j] = left + right;
            }
        }
        vout[e].x = pack_h2(bb[0], bb[1]);
        vout[e].y = pack_h2(bb[2], bb[3]);
        vout[e].z = pack_h2(bb[4], bb[5]);
        vout[e].w = pack_h2(bb[6], bb[7]);
    }

    uint4* dst = reinterpret_cast<uint4*>(g_A + (size_t)b * KTOT + i4 * KSPL);
    #pragma unroll
    for (int e = 0; e < 4; e++) dst[e] = vout[e];
    *reinterpret_cast<uint2*>(g_A + (size_t)b * KTOT + KBASE + i4) =
        *reinterpret_cast<uint2*>(sv);
}

// ---------------------------------------------------------------------------
// K3: GEMM out[16384,512] = A @ W'^T   (fp16 in, fp32 accum, mma.sync)
// EXACT R5 structure (best measured: 233us): 256 threads, 8 warps (2m x 4n),
// warp tile 64x32, 3-stage cp.async, ONE __syncthreads per chunk, 2 CTAs/SM,
// sequential K order (A-panel L2 reuse across n-tiles), LDSM-then-MMA per ks.
// ---------------------------------------------------------------------------
__device__ __forceinline__ void load_stage(uint32_t sbd, int stage,
                                           const __half* __restrict__ Ag,
                                           const __half* __restrict__ Bg,
                                           int chunk, int tid)
{
    uint32_t a0 = sbd + stage * STAGE_BYTES;
    uint32_t b0 = a0 + A_BYTES;
    const __half* Ac = Ag + chunk * BK;
    const __half* Bc = Bg + chunk * BK;
    #pragma unroll
    for (int t = 0; t < 4; t++) {                    // A: 1024 x 16B granules
        int g = tid + t * 256;
        int r = g >> 3, c = g & 7;
        cp_async16(a0 + swz(r, c * 16), Ac + (size_t)r * KTOT + c * 8);
    }
    #pragma unroll
    for (int t = 0; t < 4; t++) {                    // B: 1024 x 16B granules
        int g = tid + t * 256;
        int r = g >> 3, c = g & 7;
        cp_async16(b0 + swz(r, c * 16), Bc + (size_t)r * KTOT + c * 8);
    }
}

__global__ void __launch_bounds__(256, 2) kan_gemm_kernel(float* __restrict__ out)
{
    extern __shared__ char smem_raw[];
    uint32_t sb_raw = smem_u32(smem_raw);
    uint32_t sbd = (sb_raw + 1023u) & ~1023u;        // swizzle wants clean low bits

    int tid = threadIdx.x, wid = tid >> 5, lid = tid & 31;
    int nt = blockIdx.x, mt = blockIdx.y;
    const __half* Ag = g_A + (size_t)mt * BM * KTOT;
    const __half* Bg = g_W + (size_t)nt * BN * KTOT;

    int wm = (wid >> 2) * 64;                        // warp m offset (2 groups)
    int wn = (wid & 3) * 32;                         // warp n offset (4 groups)

    float d[4][4][4];
    #pragma unroll
    for (int mi = 0; mi < 4; mi++)
        #pragma unroll
        for (int ni = 0; ni < 4; ni++)
            #pragma unroll
            for (int q = 0; q < 4; q++) d[mi][ni][q] = 0.0f;

    // prologue: stages 0,1
    load_stage(sbd, 0, Ag, Bg, 0, tid); CP_COMMIT();
    load_stage(sbd, 1, Ag, Bg, 1, tid); CP_COMMIT();

    // per-lane ldmatrix address components
    // A (no trans): a0..a3 = m0-7/k0-7, m8-15/k0-7, m0-7/k8-15, m8-15/k8-15
    int a_lane_r = lid & 15;
    int a_lane_c = (lid >> 4) << 4;
    // B (no trans; smem [n][k] is Bmat^T for row.col mma):
    //   b-matrices: n0-7/k0-7, n0-7/k8-15, n8-15/k0-7, n8-15/k8-15
    int b_lane_r = ((lid >> 4) << 3) + (lid & 7);
    int b_lane_c = ((lid >> 3) & 1) << 4;

    for (int c = 0; c < NCHUNK; c++) {
        CP_WAIT1();
        __syncthreads();
        // safe: stage (c+2)%3 == (c-1)%3, finished by all warps before the
        // barrier above (load strictly after sync)
        if (c + 2 < NCHUNK) load_stage(sbd, (c + 2) % NSTAGE, Ag, Bg, c + 2, tid);
        CP_COMMIT();                                 // empty group keeps wait invariant

        uint32_t a0 = sbd + (c % NSTAGE) * STAGE_BYTES;
        uint32_t b0 = a0 + A_BYTES;

        #pragma unroll
        for (int ks = 0; ks < 4; ks++) {
            int kb = ks * 32;                        // 16 halfs = 32 bytes
            uint32_t Af[4][4], Bf[2][4];
            #pragma unroll
            for (int mi = 0; mi < 4; mi++) {
                int r = wm + mi * 16 + a_lane_r;
                ldm_x4(Af[mi], a0 + swz(r, kb + a_lane_c));
            }
            #pragma unroll
            for (int L = 0; L < 2; L++) {
                int r = wn + L * 16 + b_lane_r;
                ldm_x4(Bf[L], b0 + swz(r, kb + b_lane_c));
            }
            #pragma unroll
            for (int mi = 0; mi < 4; mi++)
                #pragma unroll
                for (int ni = 0; ni < 4; ni++) {
                    const uint32_t* B2 = Bf[ni >> 1] + ((ni & 1) << 1);
                    mma16816(d[mi][ni], Af[mi], B2[0], B2[1]);
                }
        }
        // no trailing barrier: next iteration's top barrier provides it
    }

    // epilogue: registers -> gmem (no smem involved, no sync needed)
    int gp = lid >> 2, t4 = lid & 3;
    #pragma unroll
    for (int mi = 0; mi < 4; mi++) {
        int row0 = mt * BM + wm + mi * 16 + gp;
        #pragma unroll
        for (int ni = 0; ni < 4; ni++) {
            int col = nt * BN + wn + ni * 8 + t4 * 2;
            float2 v0 = make_float2(d[mi][ni][0], d[mi][ni][1]);
            float2 v1 = make_float2(d[mi][ni][2], d[mi][ni][3]);
            *reinterpret_cast<float2*>(out + (size_t)row0 * OUTFEAT + col)       = v0;
            *reinterpret_cast<float2*>(out + (size_t)(row0 + 8) * OUTFEAT + col) = v1;
        }
    }
}

// ---------------------------------------------------------------------------
// Launch
// ---------------------------------------------------------------------------
extern "C" void kernel_launch(void* const* d_in, const int* in_sizes, int n_in,
                              void* d_out, int out_size)
{
    const float* x        = (const float*)d_in[0];   // (16384, 512)
    const float* grid     = (const float*)d_in[1];   // (512, 12)
    const float* base_w   = (const float*)d_in[2];   // (512, 512)
    const float* spline_w = (const float*)d_in[3];   // (512, 512, 8)
    const float* scaler   = (const float*)d_in[4];   // (512, 512)
    float* out = (float*)d_out;                      // (16384, 512)

    init_tables_kernel<<<1, 32>>>(grid);
    pack_w_kernel<<<(OUTFEAT * INFEAT) / 256, 256>>>(base_w, spline_w, scaler);
    act_kernel<<<(BATCHN * INFEAT / 4) / 256, 256>>>(x);

    cudaFuncSetAttribute(kan_gemm_kernel,
                         cudaFuncAttributeMaxDynamicSharedMemorySize, SMEM_BYTES);
    dim3 g(OUTFEAT / BN, BATCHN / BM);               // (4, 128), n fastest for L2 reuse
    kan_gemm_kernel<<<g, 256, SMEM_BYTES>>>(out);
}